// round 13
// baseline (speedup 1.0000x reference)
#include <cuda_runtime.h>
#include <cstdint>
#include <cstddef>

#define BSZ 32
#define SEQ 256
#define EMBD 256
#define HIDD 512
#define NTAG 45
#define NTOK (BSZ*SEQ)     // 8192
#define G4H  2048          // 4*HID
#define GN   4096          // both directions
#define RS   572           // lstm smem row stride (floats)

typedef unsigned long long u64v2;   // packed f32x2

__device__ __forceinline__ void fma2_(u64v2& d, u64v2 a, u64v2 b) {
    asm("fma.rn.f32x2 %0, %1, %2, %0;" : "+l"(d) : "l"(a), "l"(b));
}
__device__ __forceinline__ float unpack_sum_(u64v2 v) {
    float lo, hi;
    asm("mov.b64 {%0, %1}, %2;" : "=f"(lo), "=f"(hi) : "l"(v));
    return lo + hi;
}
__device__ __forceinline__ u64v2 pack2_(float lo, float hi) {
    u64v2 r;
    asm("mov.b64 %0, {%1, %2};" : "=l"(r) : "f"(lo), "f"(hi));
    return r;
}

// ---------------- scratch ----------------
__device__ __align__(16) float g_G[(size_t)NTOK * GN];           // input proj + bias
__device__ __align__(16) float g_hseq[2 * SEQ * BSZ * HIDD];     // [dir][t][b][h]
__device__ __align__(16) float g_em[(size_t)NTOK * NTAG];        // emissions
__device__ float g_loss[BSZ];
__device__ unsigned g_cnt4[4 * 32];                              // flat barrier counters
__device__ unsigned g_gen4[4 * 32];                              // monotonic generations

// =====================================================================
// Kernel 1: G[token][n] = dot(emb[x[token]], W[n]) + bias[n]  (f32x2)
// 2 CTAs/SM to hide L2 latency across __syncthreads gaps.
// =====================================================================
__global__ __launch_bounds__(256, 2) void gemm_in(
    const int* __restrict__ x, const float* __restrict__ emb,
    const float* __restrict__ wf, const float* __restrict__ wb,
    const float* __restrict__ bf, const float* __restrict__ bb)
{
    __shared__ float sA[16 * 132];
    __shared__ float sW[16 * 132];
    const int tid = threadIdx.x;
    const int bx = blockIdx.x;
    const int by = blockIdx.y;
    const int tx = tid & 15, ty = tid >> 4;

    u64v2 acc2[8][4];
#pragma unroll
    for (int i = 0; i < 8; ++i)
#pragma unroll
        for (int j = 0; j < 4; ++j) acc2[i][j] = 0ull;

    const int f4a = tid * 2, f4b = tid * 2 + 1;
    const int ra = f4a >> 2, qa = (f4a & 3) * 4;
    const int rb = f4b >> 2, qb = (f4b & 3) * 4;
    const float* arow_a = emb + (size_t)x[by * 128 + ra] * EMBD;
    const float* arow_b = emb + (size_t)x[by * 128 + rb] * EMBD;
    const int na = bx * 128 + ra, nb = bx * 128 + rb;
    const float* wrow_a = (na < G4H) ? (wf + (size_t)na * EMBD) : (wb + (size_t)(na - G4H) * EMBD);
    const float* wrow_b = (nb < G4H) ? (wf + (size_t)nb * EMBD) : (wb + (size_t)(nb - G4H) * EMBD);

    for (int kb = 0; kb < EMBD; kb += 16) {
        __syncthreads();
        float4 va = *(const float4*)(arow_a + kb + qa);
        float4 vb = *(const float4*)(arow_b + kb + qb);
        float4 wa = *(const float4*)(wrow_a + kb + qa);
        float4 wv = *(const float4*)(wrow_b + kb + qb);
        sA[(qa + 0) * 132 + ra] = va.x; sA[(qa + 1) * 132 + ra] = va.y;
        sA[(qa + 2) * 132 + ra] = va.z; sA[(qa + 3) * 132 + ra] = va.w;
        sA[(qb + 0) * 132 + rb] = vb.x; sA[(qb + 1) * 132 + rb] = vb.y;
        sA[(qb + 2) * 132 + rb] = vb.z; sA[(qb + 3) * 132 + rb] = vb.w;
        sW[(qa + 0) * 132 + ra] = wa.x; sW[(qa + 1) * 132 + ra] = wa.y;
        sW[(qa + 2) * 132 + ra] = wa.z; sW[(qa + 3) * 132 + ra] = wa.w;
        sW[(qb + 0) * 132 + rb] = wv.x; sW[(qb + 1) * 132 + rb] = wv.y;
        sW[(qb + 2) * 132 + rb] = wv.z; sW[(qb + 3) * 132 + rb] = wv.w;
        __syncthreads();
#pragma unroll
        for (int kk = 0; kk < 16; ++kk) {
            float4 a0 = *(const float4*)&sA[kk * 132 + ty * 8];
            float4 a1 = *(const float4*)&sA[kk * 132 + ty * 8 + 4];
            ulonglong2 b0 = *(const ulonglong2*)&sW[kk * 132 + tx * 8];
            ulonglong2 b1 = *(const ulonglong2*)&sW[kk * 132 + tx * 8 + 4];
            float av[8] = {a0.x, a0.y, a0.z, a0.w, a1.x, a1.y, a1.z, a1.w};
#pragma unroll
            for (int i = 0; i < 8; ++i) {
                u64v2 aa = pack2_(av[i], av[i]);
                fma2_(acc2[i][0], aa, b0.x);
                fma2_(acc2[i][1], aa, b0.y);
                fma2_(acc2[i][2], aa, b1.x);
                fma2_(acc2[i][3], aa, b1.y);
            }
        }
    }
    const int m0 = by * 128 + ty * 8;
    const int n0 = bx * 128 + tx * 8;
#pragma unroll
    for (int i = 0; i < 8; ++i) {
        float* dst = g_G + (size_t)(m0 + i) * GN + n0;
#pragma unroll
        for (int p = 0; p < 4; ++p) {
            float lo, hi;
            asm("mov.b64 {%0, %1}, %2;" : "=f"(lo), "=f"(hi) : "l"(acc2[i][p]));
            int n_lo = n0 + 2 * p, n_hi = n_lo + 1;
            float bias_lo = (n_lo < G4H) ? bf[n_lo] : bb[n_lo - G4H];
            float bias_hi = (n_hi < G4H) ? bf[n_hi] : bb[n_hi - G4H];
            dst[2 * p]     = lo + bias_lo;
            dst[2 * p + 1] = hi + bias_hi;
        }
    }
}

// =====================================================================
// Kernel 2: persistent bidirectional LSTM — WARP-SPECIALIZED halves.
// (proven R12 version — unchanged)
// =====================================================================
__device__ __forceinline__ float sigmoidf_(float v) { return 1.f / (1.f + __expf(-v)); }

__global__ __launch_bounds__(256) void lstm_rec(
    const float* __restrict__ whf, const float* __restrict__ whb)
{
    extern __shared__ float smemf[];
    float* sw = smemf;                                   // 32 rows x RS (shared by halves)

    const int tid = threadIdx.x;
    const int dir = blockIdx.x >> 6;
    const int blk = blockIdx.x & 63;
    const int jbase = blk * 8;
    const int half = tid >> 7;                           // batch group 0/1
    const int htid = tid & 127;
    const float* whh = dir ? whb : whf;

    float* sh  = smemf + (32 + half * 16) * RS;          // 16 rows x RS per half
    float* red = smemf + 64 * RS + half * (8 * 16 * 36); // [8 kseg][16 unit] x 36

    for (int idx = tid; idx < 32 * 128; idx += 256) {
        int row = idx >> 7;
        int q4 = idx & 127;
        int g = row >> 3, j = row & 7;
        float4 v = *(const float4*)(whh + (size_t)(g * 512 + jbase + j) * HIDD + q4 * 4);
        *(float4*)&sw[row * RS + q4 * 4 + 4 * (q4 >> 3)] = v;
    }

    const int kseg = htid >> 4;
    const int unit = htid & 15;
    const int jj = unit & 7;
    const int bo = unit >> 3;
    const int kb = kseg * 72;

    const int fj = htid & 7;
    const int fbl = htid >> 3;
    const int fb = half * 16 + fbl;
    const int jglob = jbase + fj;
    const int funit = fj + 8 * (fbl >> 3);
    const int fbb = fbl & 7;

    const int slot = (dir * 2 + half) * 32;
    unsigned gbase = 0;
    if (htid == 0) {
        asm volatile("ld.acquire.gpu.global.u32 %0, [%1];"
                     : "=r"(gbase) : "l"(&g_gen4[slot]) : "memory");
    }
    float c_state = 0.f;
    __syncthreads();
    const int barid = 1 + half;

    for (int t = 0; t < SEQ; ++t) {
        const int t_eff = dir ? (SEQ - 1 - t) : t;
        const float* Grow = g_G + (size_t)(fb * SEQ + t_eff) * GN + dir * G4H;
        float pg0 = __ldg(Grow + jglob);
        float pg1 = __ldg(Grow + 512 + jglob);
        float pg2 = __ldg(Grow + 1024 + jglob);
        float pg3 = __ldg(Grow + 1536 + jglob);

        float d0 = 0.f, d1 = 0.f, d2 = 0.f, d3 = 0.f;
        if (t > 0) {
            if (htid == 0) {
                unsigned v;
                do {
                    asm volatile("ld.acquire.gpu.global.u32 %0, [%1];"
                                 : "=r"(v) : "l"(&g_gen4[slot]) : "memory");
                } while ((unsigned)(v - gbase) < (unsigned)t);
            }
            asm volatile("bar.sync %0, %1;" :: "r"(barid), "r"(128) : "memory");
            const int prev_te = dir ? (t_eff + 1) : (t_eff - 1);
            const float* hsrc = g_hseq + (size_t)((dir * SEQ + prev_te) * BSZ + half * 16) * HIDD;
            for (int idx = htid; idx < 16 * 128; idx += 128) {
                int b = idx >> 7;
                int q4 = idx & 127;
                float4 v = __ldcg((const float4*)(hsrc + b * HIDD + q4 * 4));
                *(float4*)&sh[b * RS + q4 * 4 + 4 * (q4 >> 3)] = v;
            }
            asm volatile("bar.sync %0, %1;" :: "r"(barid), "r"(128) : "memory");
            u64v2 acc2[4][8];
#pragma unroll
            for (int g = 0; g < 4; ++g)
#pragma unroll
                for (int bb = 0; bb < 8; ++bb) acc2[g][bb] = 0ull;
            const float* w0p = &sw[jj * RS + kb];
            const float* w1p = w0p + 8 * RS;
            const float* w2p = w0p + 16 * RS;
            const float* w3p = w0p + 24 * RS;
            const float* hp  = &sh[(bo * 8) * RS + kb];
#pragma unroll
            for (int sb = 0; sb < 2; ++sb) {
                const int so = sb * 36;
#pragma unroll
                for (int kk = 0; kk < 32; kk += 4) {
                    ulonglong2 w0 = *(const ulonglong2*)(w0p + so + kk);
                    ulonglong2 w1 = *(const ulonglong2*)(w1p + so + kk);
                    ulonglong2 w2 = *(const ulonglong2*)(w2p + so + kk);
                    ulonglong2 w3 = *(const ulonglong2*)(w3p + so + kk);
#pragma unroll
                    for (int bb = 0; bb < 8; ++bb) {
                        ulonglong2 h = *(const ulonglong2*)(hp + bb * RS + so + kk);
                        fma2_(acc2[0][bb], w0.x, h.x); fma2_(acc2[0][bb], w0.y, h.y);
                        fma2_(acc2[1][bb], w1.x, h.x); fma2_(acc2[1][bb], w1.y, h.y);
                        fma2_(acc2[2][bb], w2.x, h.x); fma2_(acc2[2][bb], w2.y, h.y);
                        fma2_(acc2[3][bb], w3.x, h.x); fma2_(acc2[3][bb], w3.y, h.y);
                    }
                }
            }
            float* rp = &red[(kseg * 16 + unit) * 36];
#pragma unroll
            for (int g = 0; g < 4; ++g) {
                float s0 = unpack_sum_(acc2[g][0]);
                float s1 = unpack_sum_(acc2[g][1]);
                float s2 = unpack_sum_(acc2[g][2]);
                float s3 = unpack_sum_(acc2[g][3]);
                float s4 = unpack_sum_(acc2[g][4]);
                float s5 = unpack_sum_(acc2[g][5]);
                float s6 = unpack_sum_(acc2[g][6]);
                float s7 = unpack_sum_(acc2[g][7]);
                *(float4*)&rp[g * 8]     = make_float4(s0, s1, s2, s3);
                *(float4*)&rp[g * 8 + 4] = make_float4(s4, s5, s6, s7);
            }
            asm volatile("bar.sync %0, %1;" :: "r"(barid), "r"(128) : "memory");
#pragma unroll
            for (int s = 0; s < 8; ++s) {
                const float* rr = &red[(s * 16 + funit) * 36];
                d0 += rr[fbb];
                d1 += rr[8 + fbb];
                d2 += rr[16 + fbb];
                d3 += rr[24 + fbb];
            }
        }
        {
            float gi = pg0 + d0;
            float gf = pg1 + d1;
            float gg = pg2 + d2;
            float go = pg3 + d3;
            float iv = sigmoidf_(gi);
            float fv = sigmoidf_(gf);
            float ov = sigmoidf_(go);
            float gv = tanhf(gg);
            c_state = fv * c_state + iv * gv;
            float hv = ov * tanhf(c_state);
            __stcg(&g_hseq[(size_t)((dir * SEQ + t_eff) * BSZ + fb) * HIDD + jglob], hv);
        }
        asm volatile("bar.sync %0, %1;" :: "r"(barid), "r"(128) : "memory");
        if (htid == 0) {
            unsigned old;
            asm volatile("atom.release.gpu.global.add.u32 %0, [%1], %2;"
                         : "=r"(old) : "l"(&g_cnt4[slot]), "r"(1u) : "memory");
            if (old == 63u) {
                asm volatile("st.global.u32 [%0], %1;"
                             :: "l"(&g_cnt4[slot]), "r"(0u) : "memory");
                unsigned ng = gbase + (unsigned)t + 1u;
                asm volatile("st.release.gpu.global.u32 [%0], %1;"
                             :: "l"(&g_gen4[slot]), "r"(ng) : "memory");
            }
        }
    }
}

// =====================================================================
// Kernel 3: emissions
// =====================================================================
__device__ __forceinline__ float dot4_(float4 a, float4 b) {
    return a.x * b.x + a.y * b.y + a.z * b.z + a.w * b.w;
}

__global__ __launch_bounds__(256) void emis_k(
    const float* __restrict__ lw, const float* __restrict__ lb)
{
    __shared__ float shh[32 * 132];
    __shared__ float shw[48 * 132];
    const int tid = threadIdx.x;
    const int blk = blockIdx.x;
    const int b = blk >> 3;
    const int s0 = (blk & 7) * 32;
    const int tt = tid & 15;
    const int tg = tid >> 4;
    float acc[2][3] = {{0.f, 0.f, 0.f}, {0.f, 0.f, 0.f}};

    for (int kc = 0; kc < 1024; kc += 128) {
        __syncthreads();
        const int dk = kc >> 9;
        const int ko = kc & 511;
        for (int idx = tid; idx < 32 * 32; idx += 256) {
            int ti = idx >> 5;
            int q = (idx & 31) * 4;
            *(float4*)&shh[ti * 132 + q] =
                *(const float4*)&g_hseq[(size_t)((dk * SEQ + (s0 + ti)) * BSZ + b) * HIDD + ko + q];
        }
        for (int idx = tid; idx < 48 * 32; idx += 256) {
            int tag = idx >> 5;
            int q = (idx & 31) * 4;
            float4 v = make_float4(0.f, 0.f, 0.f, 0.f);
            if (tag < NTAG) v = *(const float4*)&lw[(size_t)tag * 1024 + kc + q];
            *(float4*)&shw[tag * 132 + q] = v;
        }
        __syncthreads();
#pragma unroll 8
        for (int kk = 0; kk < 128; kk += 4) {
            float4 h0 = *(const float4*)&shh[tt * 132 + kk];
            float4 h1 = *(const float4*)&shh[(tt + 16) * 132 + kk];
            float4 w0 = *(const float4*)&shw[tg * 132 + kk];
            float4 w1 = *(const float4*)&shw[(tg + 16) * 132 + kk];
            float4 w2 = *(const float4*)&shw[(tg + 32) * 132 + kk];
            acc[0][0] += dot4_(h0, w0); acc[0][1] += dot4_(h0, w1); acc[0][2] += dot4_(h0, w2);
            acc[1][0] += dot4_(h1, w0); acc[1][1] += dot4_(h1, w1); acc[1][2] += dot4_(h1, w2);
        }
    }
#pragma unroll
    for (int ti = 0; ti < 2; ++ti) {
        int token = b * SEQ + s0 + tt + ti * 16;
#pragma unroll
        for (int c = 0; c < 3; ++c) {
            int tag = tg + c * 16;
            if (tag < NTAG)
                g_em[(size_t)token * NTAG + tag] = acc[ti][c] + lb[tag];
        }
    }
}

// =====================================================================
// Kernel 4: CRF — one WARP per batch, REGISTER-RESIDENT alpha with
// shuffle broadcast (no smem alpha, no __syncwarp in the step loop),
// 4-way split accumulator chains. Lazy renorm every 8 steps.
// =====================================================================
__global__ __launch_bounds__(128) void crf_k(
    const int* __restrict__ tags, const float* __restrict__ st,
    const float* __restrict__ et, const float* __restrict__ tr)
{
    __shared__ float str[NTAG * NTAG];
    __shared__ float sE[NTAG * 48];
    const int tid = threadIdx.x;
    const int wid = tid >> 5;
    const int lane = tid & 31;
    const int b = blockIdx.x * 4 + wid;
    const int* tg = tags + b * SEQ;

    for (int i = tid; i < NTAG * NTAG; i += 128) str[i] = tr[i];
    __syncthreads();
    for (int idx = tid; idx < NTAG * NTAG; idx += 128) {
        int i = idx / NTAG, col = idx % NTAG;
        sE[i * 48 + col] = __expf(str[idx]);
    }
    __syncthreads();

    // ---- gold path score ----
    float part = 0.f;
    for (int s = lane; s < SEQ; s += 32) {
        int cur = tg[s];
        part += g_em[(size_t)(b * SEQ + s) * NTAG + cur];
        if (s + 1 < SEQ) part += str[cur * NTAG + tg[s + 1]];
    }
#pragma unroll
    for (int off = 16; off; off >>= 1)
        part += __shfl_xor_sync(0xffffffffu, part, off);

    // ---- forward algorithm: alpha in registers (va0: tags 0-31 by lane,
    //      va1: tags 32-44 on lanes 0-12), shuffle broadcast ----
    const int c0 = lane;
    const bool has1 = (lane < 13);
    const int c1 = has1 ? lane + 32 : 0;

    float i0 = st[c0] + g_em[(size_t)(b * SEQ) * NTAG + c0];
    float i1 = has1 ? (st[c1] + g_em[(size_t)(b * SEQ) * NTAG + c1]) : -1e30f;
    float m = fmaxf(i0, i1);
#pragma unroll
    for (int off = 16; off; off >>= 1)
        m = fmaxf(m, __shfl_xor_sync(0xffffffffu, m, off));
    float logacc = m;
    float va0 = __expf(i0 - m);
    float va1 = has1 ? __expf(i1 - m) : 0.f;

    const float* sE0 = sE + c0;
    const float* sE1 = sE + c1;

    float e0 = g_em[(size_t)(b * SEQ + 1) * NTAG + c0];
    float e1 = has1 ? g_em[(size_t)(b * SEQ + 1) * NTAG + c1] : 0.f;
    for (int t = 1; t < SEQ; ++t) {
        float n0 = 0.f, n1 = 0.f;
        if (t + 1 < SEQ) {
            n0 = g_em[(size_t)(b * SEQ + t + 1) * NTAG + c0];
            if (has1) n1 = g_em[(size_t)(b * SEQ + t + 1) * NTAG + c1];
        }
        // 4-way split accumulator chains over i
        float p0a = 0.f, p0b = 0.f, p0c = 0.f, p0d = 0.f;
        float p1a = 0.f, p1b = 0.f, p1c = 0.f, p1d = 0.f;
#pragma unroll
        for (int i = 0; i < 32; i += 4) {
            float a0 = __shfl_sync(0xffffffffu, va0, i);
            float a1 = __shfl_sync(0xffffffffu, va0, i + 1);
            float a2 = __shfl_sync(0xffffffffu, va0, i + 2);
            float a3 = __shfl_sync(0xffffffffu, va0, i + 3);
            p0a += sE0[(i    ) * 48] * a0;  p1a += sE1[(i    ) * 48] * a0;
            p0b += sE0[(i + 1) * 48] * a1;  p1b += sE1[(i + 1) * 48] * a1;
            p0c += sE0[(i + 2) * 48] * a2;  p1c += sE1[(i + 2) * 48] * a2;
            p0d += sE0[(i + 3) * 48] * a3;  p1d += sE1[(i + 3) * 48] * a3;
        }
#pragma unroll
        for (int i = 32; i < 44; i += 4) {
            float a0 = __shfl_sync(0xffffffffu, va1, i - 32);
            float a1 = __shfl_sync(0xffffffffu, va1, i - 31);
            float a2 = __shfl_sync(0xffffffffu, va1, i - 30);
            float a3 = __shfl_sync(0xffffffffu, va1, i - 29);
            p0a += sE0[(i    ) * 48] * a0;  p1a += sE1[(i    ) * 48] * a0;
            p0b += sE0[(i + 1) * 48] * a1;  p1b += sE1[(i + 1) * 48] * a1;
            p0c += sE0[(i + 2) * 48] * a2;  p1c += sE1[(i + 2) * 48] * a2;
            p0d += sE0[(i + 3) * 48] * a3;  p1d += sE1[(i + 3) * 48] * a3;
        }
        {
            float a44 = __shfl_sync(0xffffffffu, va1, 12);
            p0a += sE0[44 * 48] * a44;
            p1a += sE1[44 * 48] * a44;
        }
        float s0 = (p0a + p0b) + (p0c + p0d);
        float s1 = (p1a + p1b) + (p1c + p1d);
        va0 = s0 * __expf(e0);
        va1 = has1 ? (s1 * __expf(e1)) : 0.f;
        if ((t & 7) == 0) {
            float mm = fmaxf(va0, va1);
#pragma unroll
            for (int off = 16; off; off >>= 1)
                mm = fmaxf(mm, __shfl_xor_sync(0xffffffffu, mm, off));
            float inv = 1.f / mm;
            va0 *= inv;
            va1 *= inv;
            logacc += __logf(mm);
        }
        e0 = n0; e1 = n1;
    }

    float ssum = va0 * __expf(et[c0]);
    if (has1) ssum += va1 * __expf(et[c1]);
#pragma unroll
    for (int off = 16; off; off >>= 1)
        ssum += __shfl_xor_sync(0xffffffffu, ssum, off);

    if (lane == 0) {
        float sc = part + st[tg[0]] + et[tg[SEQ - 1]];
        float logZ = logacc + __logf(ssum);
        g_loss[b] = logZ - sc;
    }
}

__global__ void final_reduce(float* __restrict__ out)
{
    if (threadIdx.x == 0) {
        float s = 0.f;
        for (int i = 0; i < BSZ; ++i) s += g_loss[i];
        out[0] = s / (float)BSZ;
    }
}

// =====================================================================
extern "C" void kernel_launch(void* const* d_in, const int* in_sizes, int n_in,
                              void* d_out, int out_size)
{
    (void)in_sizes; (void)n_in; (void)out_size;
    const int*   x   = (const int*)d_in[0];
    const int*   tgs = (const int*)d_in[1];
    const float* emb = (const float*)d_in[2];
    const float* wif = (const float*)d_in[3];
    const float* whf = (const float*)d_in[4];
    const float* bf  = (const float*)d_in[5];
    const float* wib = (const float*)d_in[6];
    const float* whb = (const float*)d_in[7];
    const float* bb  = (const float*)d_in[8];
    const float* lw  = (const float*)d_in[9];
    const float* lb  = (const float*)d_in[10];
    const float* st  = (const float*)d_in[11];
    const float* et  = (const float*)d_in[12];
    const float* tr  = (const float*)d_in[13];
    float* out = (float*)d_out;

    const int rec_smem = (64 * RS + 2 * 8 * 16 * 36) * 4;   // 183296 B
    cudaFuncSetAttribute(lstm_rec, cudaFuncAttributeMaxDynamicSharedMemorySize, rec_smem);

    dim3 gemm_grid(32, 64);
    gemm_in<<<gemm_grid, 256>>>(x, emb, wif, wib, bf, bb);
    lstm_rec<<<128, 256, rec_smem>>>(whf, whb);
    emis_k<<<256, 256>>>(lw, lb);
    crf_k<<<8, 128>>>(tgs, st, et, tr);
    final_reduce<<<1, 32>>>(out);
}

// round 14
// speedup vs baseline: 1.0446x; 1.0446x over previous
#include <cuda_runtime.h>
#include <cstdint>
#include <cstddef>

#define BSZ 32
#define SEQ 256
#define EMBD 256
#define HIDD 512
#define NTAG 45
#define NTOK (BSZ*SEQ)     // 8192
#define G4H  2048          // 4*HID
#define GN   4096          // both directions
#define RS   572           // lstm smem row stride (floats)

typedef unsigned long long u64v2;   // packed f32x2

__device__ __forceinline__ void fma2_(u64v2& d, u64v2 a, u64v2 b) {
    asm("fma.rn.f32x2 %0, %1, %2, %0;" : "+l"(d) : "l"(a), "l"(b));
}
__device__ __forceinline__ float unpack_sum_(u64v2 v) {
    float lo, hi;
    asm("mov.b64 {%0, %1}, %2;" : "=f"(lo), "=f"(hi) : "l"(v));
    return lo + hi;
}
__device__ __forceinline__ u64v2 pack2_(float lo, float hi) {
    u64v2 r;
    asm("mov.b64 %0, {%1, %2};" : "=l"(r) : "f"(lo), "f"(hi));
    return r;
}

// ---------------- scratch ----------------
__device__ __align__(16) float g_G[(size_t)NTOK * GN];           // input proj + bias
__device__ __align__(16) float g_hseq[2 * SEQ * BSZ * HIDD];     // [dir][t][b][h]
__device__ __align__(16) float g_em[(size_t)NTOK * NTAG];        // emissions
__device__ float g_loss[BSZ];
__device__ unsigned g_cnt4[4 * 32];                              // flat barrier counters
__device__ unsigned g_gen4[4 * 32];                              // monotonic generations

// =====================================================================
// Kernel 1: G[token][n] = dot(emb[x[token]], W[n]) + bias[n]  (f32x2)
// Software-pipelined: next chunk's LDGs issue before compute; 2 CTAs/SM.
// =====================================================================
__global__ __launch_bounds__(256, 2) void gemm_in(
    const int* __restrict__ x, const float* __restrict__ emb,
    const float* __restrict__ wf, const float* __restrict__ wb,
    const float* __restrict__ bf, const float* __restrict__ bb)
{
    __shared__ float sA[16 * 132];
    __shared__ float sW[16 * 132];
    const int tid = threadIdx.x;
    const int bx = blockIdx.x;
    const int by = blockIdx.y;
    const int tx = tid & 15, ty = tid >> 4;

    u64v2 acc2[8][4];
#pragma unroll
    for (int i = 0; i < 8; ++i)
#pragma unroll
        for (int j = 0; j < 4; ++j) acc2[i][j] = 0ull;

    const int f4a = tid * 2, f4b = tid * 2 + 1;
    const int ra = f4a >> 2, qa = (f4a & 3) * 4;
    const int rb = f4b >> 2, qb = (f4b & 3) * 4;
    const float* arow_a = emb + (size_t)x[by * 128 + ra] * EMBD;
    const float* arow_b = emb + (size_t)x[by * 128 + rb] * EMBD;
    const int na = bx * 128 + ra, nb = bx * 128 + rb;
    const float* wrow_a = (na < G4H) ? (wf + (size_t)na * EMBD) : (wb + (size_t)(na - G4H) * EMBD);
    const float* wrow_b = (nb < G4H) ? (wf + (size_t)nb * EMBD) : (wb + (size_t)(nb - G4H) * EMBD);

    // prologue: prefetch chunk 0
    float4 va = *(const float4*)(arow_a + qa);
    float4 vb = *(const float4*)(arow_b + qb);
    float4 wa = *(const float4*)(wrow_a + qa);
    float4 wv = *(const float4*)(wrow_b + qb);

    for (int kb = 0; kb < EMBD; kb += 16) {
        // store prefetched chunk to smem (transposed)
        sA[(qa + 0) * 132 + ra] = va.x; sA[(qa + 1) * 132 + ra] = va.y;
        sA[(qa + 2) * 132 + ra] = va.z; sA[(qa + 3) * 132 + ra] = va.w;
        sA[(qb + 0) * 132 + rb] = vb.x; sA[(qb + 1) * 132 + rb] = vb.y;
        sA[(qb + 2) * 132 + rb] = vb.z; sA[(qb + 3) * 132 + rb] = vb.w;
        sW[(qa + 0) * 132 + ra] = wa.x; sW[(qa + 1) * 132 + ra] = wa.y;
        sW[(qa + 2) * 132 + ra] = wa.z; sW[(qa + 3) * 132 + ra] = wa.w;
        sW[(qb + 0) * 132 + rb] = wv.x; sW[(qb + 1) * 132 + rb] = wv.y;
        sW[(qb + 2) * 132 + rb] = wv.z; sW[(qb + 3) * 132 + rb] = wv.w;
        __syncthreads();
        // prefetch next chunk (LDGs overlap the compute below)
        if (kb + 16 < EMBD) {
            va = *(const float4*)(arow_a + kb + 16 + qa);
            vb = *(const float4*)(arow_b + kb + 16 + qb);
            wa = *(const float4*)(wrow_a + kb + 16 + qa);
            wv = *(const float4*)(wrow_b + kb + 16 + qb);
        }
#pragma unroll
        for (int kk = 0; kk < 16; ++kk) {
            float4 a0 = *(const float4*)&sA[kk * 132 + ty * 8];
            float4 a1 = *(const float4*)&sA[kk * 132 + ty * 8 + 4];
            ulonglong2 b0 = *(const ulonglong2*)&sW[kk * 132 + tx * 8];
            ulonglong2 b1 = *(const ulonglong2*)&sW[kk * 132 + tx * 8 + 4];
            float av[8] = {a0.x, a0.y, a0.z, a0.w, a1.x, a1.y, a1.z, a1.w};
#pragma unroll
            for (int i = 0; i < 8; ++i) {
                u64v2 aa = pack2_(av[i], av[i]);
                fma2_(acc2[i][0], aa, b0.x);
                fma2_(acc2[i][1], aa, b0.y);
                fma2_(acc2[i][2], aa, b1.x);
                fma2_(acc2[i][3], aa, b1.y);
            }
        }
        __syncthreads();
    }
    const int m0 = by * 128 + ty * 8;
    const int n0 = bx * 128 + tx * 8;
#pragma unroll
    for (int i = 0; i < 8; ++i) {
        float* dst = g_G + (size_t)(m0 + i) * GN + n0;
#pragma unroll
        for (int p = 0; p < 4; ++p) {
            float lo, hi;
            asm("mov.b64 {%0, %1}, %2;" : "=f"(lo), "=f"(hi) : "l"(acc2[i][p]));
            int n_lo = n0 + 2 * p, n_hi = n_lo + 1;
            float bias_lo = (n_lo < G4H) ? bf[n_lo] : bb[n_lo - G4H];
            float bias_hi = (n_hi < G4H) ? bf[n_hi] : bb[n_hi - G4H];
            dst[2 * p]     = lo + bias_lo;
            dst[2 * p + 1] = hi + bias_hi;
        }
    }
}

// =====================================================================
// Kernel 2: persistent bidirectional LSTM — WARP-SPECIALIZED halves.
// (proven R12 version — unchanged)
// =====================================================================
__device__ __forceinline__ float sigmoidf_(float v) { return 1.f / (1.f + __expf(-v)); }

__global__ __launch_bounds__(256) void lstm_rec(
    const float* __restrict__ whf, const float* __restrict__ whb)
{
    extern __shared__ float smemf[];
    float* sw = smemf;                                   // 32 rows x RS (shared by halves)

    const int tid = threadIdx.x;
    const int dir = blockIdx.x >> 6;
    const int blk = blockIdx.x & 63;
    const int jbase = blk * 8;
    const int half = tid >> 7;                           // batch group 0/1
    const int htid = tid & 127;
    const float* whh = dir ? whb : whf;

    float* sh  = smemf + (32 + half * 16) * RS;          // 16 rows x RS per half
    float* red = smemf + 64 * RS + half * (8 * 16 * 36); // [8 kseg][16 unit] x 36

    for (int idx = tid; idx < 32 * 128; idx += 256) {
        int row = idx >> 7;
        int q4 = idx & 127;
        int g = row >> 3, j = row & 7;
        float4 v = *(const float4*)(whh + (size_t)(g * 512 + jbase + j) * HIDD + q4 * 4);
        *(float4*)&sw[row * RS + q4 * 4 + 4 * (q4 >> 3)] = v;
    }

    const int kseg = htid >> 4;
    const int unit = htid & 15;
    const int jj = unit & 7;
    const int bo = unit >> 3;
    const int kb = kseg * 72;

    const int fj = htid & 7;
    const int fbl = htid >> 3;
    const int fb = half * 16 + fbl;
    const int jglob = jbase + fj;
    const int funit = fj + 8 * (fbl >> 3);
    const int fbb = fbl & 7;

    const int slot = (dir * 2 + half) * 32;
    unsigned gbase = 0;
    if (htid == 0) {
        asm volatile("ld.acquire.gpu.global.u32 %0, [%1];"
                     : "=r"(gbase) : "l"(&g_gen4[slot]) : "memory");
    }
    float c_state = 0.f;
    __syncthreads();
    const int barid = 1 + half;

    for (int t = 0; t < SEQ; ++t) {
        const int t_eff = dir ? (SEQ - 1 - t) : t;
        const float* Grow = g_G + (size_t)(fb * SEQ + t_eff) * GN + dir * G4H;
        float pg0 = __ldg(Grow + jglob);
        float pg1 = __ldg(Grow + 512 + jglob);
        float pg2 = __ldg(Grow + 1024 + jglob);
        float pg3 = __ldg(Grow + 1536 + jglob);

        float d0 = 0.f, d1 = 0.f, d2 = 0.f, d3 = 0.f;
        if (t > 0) {
            if (htid == 0) {
                unsigned v;
                do {
                    asm volatile("ld.acquire.gpu.global.u32 %0, [%1];"
                                 : "=r"(v) : "l"(&g_gen4[slot]) : "memory");
                } while ((unsigned)(v - gbase) < (unsigned)t);
            }
            asm volatile("bar.sync %0, %1;" :: "r"(barid), "r"(128) : "memory");
            const int prev_te = dir ? (t_eff + 1) : (t_eff - 1);
            const float* hsrc = g_hseq + (size_t)((dir * SEQ + prev_te) * BSZ + half * 16) * HIDD;
            for (int idx = htid; idx < 16 * 128; idx += 128) {
                int b = idx >> 7;
                int q4 = idx & 127;
                float4 v = __ldcg((const float4*)(hsrc + b * HIDD + q4 * 4));
                *(float4*)&sh[b * RS + q4 * 4 + 4 * (q4 >> 3)] = v;
            }
            asm volatile("bar.sync %0, %1;" :: "r"(barid), "r"(128) : "memory");
            u64v2 acc2[4][8];
#pragma unroll
            for (int g = 0; g < 4; ++g)
#pragma unroll
                for (int bb = 0; bb < 8; ++bb) acc2[g][bb] = 0ull;
            const float* w0p = &sw[jj * RS + kb];
            const float* w1p = w0p + 8 * RS;
            const float* w2p = w0p + 16 * RS;
            const float* w3p = w0p + 24 * RS;
            const float* hp  = &sh[(bo * 8) * RS + kb];
#pragma unroll
            for (int sb = 0; sb < 2; ++sb) {
                const int so = sb * 36;
#pragma unroll
                for (int kk = 0; kk < 32; kk += 4) {
                    ulonglong2 w0 = *(const ulonglong2*)(w0p + so + kk);
                    ulonglong2 w1 = *(const ulonglong2*)(w1p + so + kk);
                    ulonglong2 w2 = *(const ulonglong2*)(w2p + so + kk);
                    ulonglong2 w3 = *(const ulonglong2*)(w3p + so + kk);
#pragma unroll
                    for (int bb = 0; bb < 8; ++bb) {
                        ulonglong2 h = *(const ulonglong2*)(hp + bb * RS + so + kk);
                        fma2_(acc2[0][bb], w0.x, h.x); fma2_(acc2[0][bb], w0.y, h.y);
                        fma2_(acc2[1][bb], w1.x, h.x); fma2_(acc2[1][bb], w1.y, h.y);
                        fma2_(acc2[2][bb], w2.x, h.x); fma2_(acc2[2][bb], w2.y, h.y);
                        fma2_(acc2[3][bb], w3.x, h.x); fma2_(acc2[3][bb], w3.y, h.y);
                    }
                }
            }
            float* rp = &red[(kseg * 16 + unit) * 36];
#pragma unroll
            for (int g = 0; g < 4; ++g) {
                float s0 = unpack_sum_(acc2[g][0]);
                float s1 = unpack_sum_(acc2[g][1]);
                float s2 = unpack_sum_(acc2[g][2]);
                float s3 = unpack_sum_(acc2[g][3]);
                float s4 = unpack_sum_(acc2[g][4]);
                float s5 = unpack_sum_(acc2[g][5]);
                float s6 = unpack_sum_(acc2[g][6]);
                float s7 = unpack_sum_(acc2[g][7]);
                *(float4*)&rp[g * 8]     = make_float4(s0, s1, s2, s3);
                *(float4*)&rp[g * 8 + 4] = make_float4(s4, s5, s6, s7);
            }
            asm volatile("bar.sync %0, %1;" :: "r"(barid), "r"(128) : "memory");
#pragma unroll
            for (int s = 0; s < 8; ++s) {
                const float* rr = &red[(s * 16 + funit) * 36];
                d0 += rr[fbb];
                d1 += rr[8 + fbb];
                d2 += rr[16 + fbb];
                d3 += rr[24 + fbb];
            }
        }
        {
            float gi = pg0 + d0;
            float gf = pg1 + d1;
            float gg = pg2 + d2;
            float go = pg3 + d3;
            float iv = sigmoidf_(gi);
            float fv = sigmoidf_(gf);
            float ov = sigmoidf_(go);
            float gv = tanhf(gg);
            c_state = fv * c_state + iv * gv;
            float hv = ov * tanhf(c_state);
            __stcg(&g_hseq[(size_t)((dir * SEQ + t_eff) * BSZ + fb) * HIDD + jglob], hv);
        }
        asm volatile("bar.sync %0, %1;" :: "r"(barid), "r"(128) : "memory");
        if (htid == 0) {
            unsigned old;
            asm volatile("atom.release.gpu.global.add.u32 %0, [%1], %2;"
                         : "=r"(old) : "l"(&g_cnt4[slot]), "r"(1u) : "memory");
            if (old == 63u) {
                asm volatile("st.global.u32 [%0], %1;"
                             :: "l"(&g_cnt4[slot]), "r"(0u) : "memory");
                unsigned ng = gbase + (unsigned)t + 1u;
                asm volatile("st.release.gpu.global.u32 [%0], %1;"
                             :: "l"(&g_gen4[slot]), "r"(ng) : "memory");
            }
        }
    }
}

// =====================================================================
// Kernel 3: emissions
// =====================================================================
__device__ __forceinline__ float dot4_(float4 a, float4 b) {
    return a.x * b.x + a.y * b.y + a.z * b.z + a.w * b.w;
}

__global__ __launch_bounds__(256) void emis_k(
    const float* __restrict__ lw, const float* __restrict__ lb)
{
    __shared__ float shh[32 * 132];
    __shared__ float shw[48 * 132];
    const int tid = threadIdx.x;
    const int blk = blockIdx.x;
    const int b = blk >> 3;
    const int s0 = (blk & 7) * 32;
    const int tt = tid & 15;
    const int tg = tid >> 4;
    float acc[2][3] = {{0.f, 0.f, 0.f}, {0.f, 0.f, 0.f}};

    for (int kc = 0; kc < 1024; kc += 128) {
        __syncthreads();
        const int dk = kc >> 9;
        const int ko = kc & 511;
        for (int idx = tid; idx < 32 * 32; idx += 256) {
            int ti = idx >> 5;
            int q = (idx & 31) * 4;
            *(float4*)&shh[ti * 132 + q] =
                *(const float4*)&g_hseq[(size_t)((dk * SEQ + (s0 + ti)) * BSZ + b) * HIDD + ko + q];
        }
        for (int idx = tid; idx < 48 * 32; idx += 256) {
            int tag = idx >> 5;
            int q = (idx & 31) * 4;
            float4 v = make_float4(0.f, 0.f, 0.f, 0.f);
            if (tag < NTAG) v = *(const float4*)&lw[(size_t)tag * 1024 + kc + q];
            *(float4*)&shw[tag * 132 + q] = v;
        }
        __syncthreads();
#pragma unroll 8
        for (int kk = 0; kk < 128; kk += 4) {
            float4 h0 = *(const float4*)&shh[tt * 132 + kk];
            float4 h1 = *(const float4*)&shh[(tt + 16) * 132 + kk];
            float4 w0 = *(const float4*)&shw[tg * 132 + kk];
            float4 w1 = *(const float4*)&shw[(tg + 16) * 132 + kk];
            float4 w2 = *(const float4*)&shw[(tg + 32) * 132 + kk];
            acc[0][0] += dot4_(h0, w0); acc[0][1] += dot4_(h0, w1); acc[0][2] += dot4_(h0, w2);
            acc[1][0] += dot4_(h1, w0); acc[1][1] += dot4_(h1, w1); acc[1][2] += dot4_(h1, w2);
        }
    }
#pragma unroll
    for (int ti = 0; ti < 2; ++ti) {
        int token = b * SEQ + s0 + tt + ti * 16;
#pragma unroll
        for (int c = 0; c < 3; ++c) {
            int tag = tg + c * 16;
            if (tag < NTAG)
                g_em[(size_t)token * NTAG + tag] = acc[ti][c] + lb[tag];
        }
    }
}

// =====================================================================
// Kernel 4: CRF — one WARP per batch, smem alpha ping-pong (PROVEN R12
// version, 147us). Exp-domain forward, lazy renorm every 8 steps.
// =====================================================================
__global__ __launch_bounds__(128) void crf_k(
    const int* __restrict__ tags, const float* __restrict__ st,
    const float* __restrict__ et, const float* __restrict__ tr)
{
    __shared__ float str[NTAG * NTAG];
    __shared__ float sE[NTAG * 48];
    __shared__ float sa[4][2][48];
    const int tid = threadIdx.x;
    const int wid = tid >> 5;
    const int lane = tid & 31;
    const int b = blockIdx.x * 4 + wid;
    const int* tg = tags + b * SEQ;

    for (int i = tid; i < NTAG * NTAG; i += 128) str[i] = tr[i];
    __syncthreads();
    for (int idx = tid; idx < NTAG * NTAG; idx += 128) {
        int i = idx / NTAG, col = idx % NTAG;
        sE[i * 48 + col] = __expf(str[idx]);
    }
    __syncthreads();

    float part = 0.f;
    for (int s = lane; s < SEQ; s += 32) {
        int cur = tg[s];
        part += g_em[(size_t)(b * SEQ + s) * NTAG + cur];
        if (s + 1 < SEQ) part += str[cur * NTAG + tg[s + 1]];
    }
#pragma unroll
    for (int off = 16; off; off >>= 1)
        part += __shfl_xor_sync(0xffffffffu, part, off);

    const int c0 = lane;
    const bool has1 = (lane < 13);
    const int c1 = has1 ? lane + 32 : lane;
    float* a0 = sa[wid][0];
    float* a1 = sa[wid][1];

    float i0 = st[c0] + g_em[(size_t)(b * SEQ) * NTAG + c0];
    float i1 = has1 ? (st[c1] + g_em[(size_t)(b * SEQ) * NTAG + c1]) : -1e30f;
    float m = fmaxf(i0, i1);
#pragma unroll
    for (int off = 16; off; off >>= 1)
        m = fmaxf(m, __shfl_xor_sync(0xffffffffu, m, off));
    float logacc = m;
    a0[c0] = __expf(i0 - m);
    if (has1) a0[c1] = __expf(i1 - m);
    __syncwarp();

    float e0 = g_em[(size_t)(b * SEQ + 1) * NTAG + c0];
    float e1 = has1 ? g_em[(size_t)(b * SEQ + 1) * NTAG + c1] : 0.f;
    int cur = 0;
    for (int t = 1; t < SEQ; ++t) {
        float n0 = 0.f, n1 = 0.f;
        if (t + 1 < SEQ) {
            n0 = g_em[(size_t)(b * SEQ + t + 1) * NTAG + c0];
            if (has1) n1 = g_em[(size_t)(b * SEQ + t + 1) * NTAG + c1];
        }
        const float* a = cur ? a1 : a0;
        float* an = cur ? a0 : a1;
        float s0 = 0.f, s1 = 0.f;
#pragma unroll 9
        for (int i = 0; i < NTAG; ++i) {
            float ai = a[i];
            s0 += sE[i * 48 + c0] * ai;
            s1 += sE[i * 48 + c1] * ai;
        }
        float v0 = s0 * __expf(e0);
        an[c0] = v0;
        float v1 = 0.f;
        if (has1) { v1 = s1 * __expf(e1); an[c1] = v1; }
        __syncwarp();
        cur ^= 1;
        if ((t & 7) == 0) {
            float mm = fmaxf(v0, v1);
#pragma unroll
            for (int off = 16; off; off >>= 1)
                mm = fmaxf(mm, __shfl_xor_sync(0xffffffffu, mm, off));
            float inv = 1.f / mm;
            float* ac = cur ? a1 : a0;
            ac[c0] *= inv;
            if (has1) ac[c1] *= inv;
            logacc += __logf(mm);
            __syncwarp();
        }
        e0 = n0; e1 = n1;
    }

    const float* af = cur ? a1 : a0;
    float ssum = af[c0] * __expf(et[c0]);
    if (has1) ssum += af[c1] * __expf(et[c1]);
#pragma unroll
    for (int off = 16; off; off >>= 1)
        ssum += __shfl_xor_sync(0xffffffffu, ssum, off);

    if (lane == 0) {
        float sc = part + st[tg[0]] + et[tg[SEQ - 1]];
        float logZ = logacc + __logf(ssum);
        g_loss[b] = logZ - sc;
    }
}

__global__ void final_reduce(float* __restrict__ out)
{
    if (threadIdx.x == 0) {
        float s = 0.f;
        for (int i = 0; i < BSZ; ++i) s += g_loss[i];
        out[0] = s / (float)BSZ;
    }
}

// =====================================================================
extern "C" void kernel_launch(void* const* d_in, const int* in_sizes, int n_in,
                              void* d_out, int out_size)
{
    (void)in_sizes; (void)n_in; (void)out_size;
    const int*   x   = (const int*)d_in[0];
    const int*   tgs = (const int*)d_in[1];
    const float* emb = (const float*)d_in[2];
    const float* wif = (const float*)d_in[3];
    const float* whf = (const float*)d_in[4];
    const float* bf  = (const float*)d_in[5];
    const float* wib = (const float*)d_in[6];
    const float* whb = (const float*)d_in[7];
    const float* bb  = (const float*)d_in[8];
    const float* lw  = (const float*)d_in[9];
    const float* lb  = (const float*)d_in[10];
    const float* st  = (const float*)d_in[11];
    const float* et  = (const float*)d_in[12];
    const float* tr  = (const float*)d_in[13];
    float* out = (float*)d_out;

    const int rec_smem = (64 * RS + 2 * 8 * 16 * 36) * 4;   // 183296 B
    cudaFuncSetAttribute(lstm_rec, cudaFuncAttributeMaxDynamicSharedMemorySize, rec_smem);

    dim3 gemm_grid(32, 64);
    gemm_in<<<gemm_grid, 256>>>(x, emb, wif, wib, bf, bb);
    lstm_rec<<<128, 256, rec_smem>>>(whf, whb);
    emis_k<<<256, 256>>>(lw, lb);
    crf_k<<<8, 128>>>(tgs, st, et, tr);
    final_reduce<<<1, 32>>>(out);
}

// round 15
// speedup vs baseline: 1.1007x; 1.0537x over previous
#include <cuda_runtime.h>
#include <cstdint>
#include <cstddef>

#define BSZ 32
#define SEQ 256
#define EMBD 256
#define HIDD 512
#define NTAG 45
#define NTOK (BSZ*SEQ)     // 8192
#define G4H  2048          // 4*HID
#define GN   4096          // both directions
#define RS   572           // lstm smem row stride (floats)

typedef unsigned long long u64v2;   // packed f32x2

__device__ __forceinline__ void fma2_(u64v2& d, u64v2 a, u64v2 b) {
    asm("fma.rn.f32x2 %0, %1, %2, %0;" : "+l"(d) : "l"(a), "l"(b));
}
__device__ __forceinline__ float unpack_sum_(u64v2 v) {
    float lo, hi;
    asm("mov.b64 {%0, %1}, %2;" : "=f"(lo), "=f"(hi) : "l"(v));
    return lo + hi;
}
__device__ __forceinline__ u64v2 pack2_(float lo, float hi) {
    u64v2 r;
    asm("mov.b64 %0, {%1, %2};" : "=l"(r) : "f"(lo), "f"(hi));
    return r;
}

// ---------------- scratch ----------------
__device__ __align__(16) float g_G[(size_t)NTOK * GN];           // input proj + bias
__device__ __align__(16) float g_hseq[2 * SEQ * BSZ * HIDD];     // [dir][t][b][h]
__device__ __align__(16) float g_em[(size_t)NTOK * NTAG];        // emissions
__device__ float g_loss[BSZ];
__device__ unsigned g_cnt4[8 * 32];                              // flat barrier counters (8 slots)
__device__ unsigned g_gen4[8 * 32];                              // monotonic generations

// =====================================================================
// Kernel 1: G[token][n] = dot(emb[x[token]], W[n]) + bias[n]  (f32x2)
// =====================================================================
__global__ __launch_bounds__(256, 2) void gemm_in(
    const int* __restrict__ x, const float* __restrict__ emb,
    const float* __restrict__ wf, const float* __restrict__ wb,
    const float* __restrict__ bf, const float* __restrict__ bb)
{
    __shared__ float sA[16 * 132];
    __shared__ float sW[16 * 132];
    const int tid = threadIdx.x;
    const int bx = blockIdx.x;
    const int by = blockIdx.y;
    const int tx = tid & 15, ty = tid >> 4;

    u64v2 acc2[8][4];
#pragma unroll
    for (int i = 0; i < 8; ++i)
#pragma unroll
        for (int j = 0; j < 4; ++j) acc2[i][j] = 0ull;

    const int f4a = tid * 2, f4b = tid * 2 + 1;
    const int ra = f4a >> 2, qa = (f4a & 3) * 4;
    const int rb = f4b >> 2, qb = (f4b & 3) * 4;
    const float* arow_a = emb + (size_t)x[by * 128 + ra] * EMBD;
    const float* arow_b = emb + (size_t)x[by * 128 + rb] * EMBD;
    const int na = bx * 128 + ra, nb = bx * 128 + rb;
    const float* wrow_a = (na < G4H) ? (wf + (size_t)na * EMBD) : (wb + (size_t)(na - G4H) * EMBD);
    const float* wrow_b = (nb < G4H) ? (wf + (size_t)nb * EMBD) : (wb + (size_t)(nb - G4H) * EMBD);

    for (int kb = 0; kb < EMBD; kb += 16) {
        __syncthreads();
        float4 va = *(const float4*)(arow_a + kb + qa);
        float4 vb = *(const float4*)(arow_b + kb + qb);
        float4 wa = *(const float4*)(wrow_a + kb + qa);
        float4 wv = *(const float4*)(wrow_b + kb + qb);
        sA[(qa + 0) * 132 + ra] = va.x; sA[(qa + 1) * 132 + ra] = va.y;
        sA[(qa + 2) * 132 + ra] = va.z; sA[(qa + 3) * 132 + ra] = va.w;
        sA[(qb + 0) * 132 + rb] = vb.x; sA[(qb + 1) * 132 + rb] = vb.y;
        sA[(qb + 2) * 132 + rb] = vb.z; sA[(qb + 3) * 132 + rb] = vb.w;
        sW[(qa + 0) * 132 + ra] = wa.x; sW[(qa + 1) * 132 + ra] = wa.y;
        sW[(qa + 2) * 132 + ra] = wa.z; sW[(qa + 3) * 132 + ra] = wa.w;
        sW[(qb + 0) * 132 + rb] = wv.x; sW[(qb + 1) * 132 + rb] = wv.y;
        sW[(qb + 2) * 132 + rb] = wv.z; sW[(qb + 3) * 132 + rb] = wv.w;
        __syncthreads();
#pragma unroll
        for (int kk = 0; kk < 16; ++kk) {
            float4 a0 = *(const float4*)&sA[kk * 132 + ty * 8];
            float4 a1 = *(const float4*)&sA[kk * 132 + ty * 8 + 4];
            ulonglong2 b0 = *(const ulonglong2*)&sW[kk * 132 + tx * 8];
            ulonglong2 b1 = *(const ulonglong2*)&sW[kk * 132 + tx * 8 + 4];
            float av[8] = {a0.x, a0.y, a0.z, a0.w, a1.x, a1.y, a1.z, a1.w};
#pragma unroll
            for (int i = 0; i < 8; ++i) {
                u64v2 aa = pack2_(av[i], av[i]);
                fma2_(acc2[i][0], aa, b0.x);
                fma2_(acc2[i][1], aa, b0.y);
                fma2_(acc2[i][2], aa, b1.x);
                fma2_(acc2[i][3], aa, b1.y);
            }
        }
    }
    const int m0 = by * 128 + ty * 8;
    const int n0 = bx * 128 + tx * 8;
#pragma unroll
    for (int i = 0; i < 8; ++i) {
        float* dst = g_G + (size_t)(m0 + i) * GN + n0;
#pragma unroll
        for (int p = 0; p < 4; ++p) {
            float lo, hi;
            asm("mov.b64 {%0, %1}, %2;" : "=f"(lo), "=f"(hi) : "l"(acc2[i][p]));
            int n_lo = n0 + 2 * p, n_hi = n_lo + 1;
            float bias_lo = (n_lo < G4H) ? bf[n_lo] : bb[n_lo - G4H];
            float bias_hi = (n_hi < G4H) ? bf[n_hi] : bb[n_hi - G4H];
            dst[2 * p]     = lo + bias_lo;
            dst[2 * p + 1] = hi + bias_hi;
        }
    }
}

// =====================================================================
// Kernel 2: persistent bidirectional LSTM — FOUR independent streams
// (quarters of 8 batches, 2 warps each). Each quarter runs lock-step
// with its own named barrier + inter-block slot; SMSPs interleave
// warps from two different quarters, hiding barrier latency.
// =====================================================================
__device__ __forceinline__ float sigmoidf_(float v) { return 1.f / (1.f + __expf(-v)); }

__global__ __launch_bounds__(256) void lstm_rec(
    const float* __restrict__ whf, const float* __restrict__ whb)
{
    extern __shared__ float smemf[];
    float* sw = smemf;                                   // 32 rows x RS (shared)

    const int tid = threadIdx.x;
    const int dir = blockIdx.x >> 6;
    const int blk = blockIdx.x & 63;
    const int jbase = blk * 8;
    const int quarter = tid >> 6;                        // 0..3 (8 batches each)
    const int qtid = tid & 63;
    const float* whh = dir ? whb : whf;

    float* sh  = smemf + (32 + quarter * 8) * RS;        // 8 rows x RS per quarter
    float* red = smemf + 64 * RS + quarter * (8 * 8 * 36); // [8 kseg][8 jj] x 36

    // cooperative w_hh load (all 256 threads), k-swizzled
    for (int idx = tid; idx < 32 * 128; idx += 256) {
        int row = idx >> 7;
        int q4 = idx & 127;
        int g = row >> 3, j = row & 7;
        float4 v = *(const float4*)(whh + (size_t)(g * 512 + jbase + j) * HIDD + q4 * 4);
        *(float4*)&sw[row * RS + q4 * 4 + 4 * (q4 >> 3)] = v;
    }

    // dot decomposition within quarter: 8 ksegs (64 k) x 8 jj
    const int kseg = qtid >> 3;          // 0..7
    const int jj = qtid & 7;
    const int kb = kseg * 72;            // swizzled 64-k base

    // finalize decomposition: thread owns (fj, fbb)
    const int fj = qtid & 7;
    const int fbb = qtid >> 3;           // 0..7 batch within quarter
    const int fb = quarter * 8 + fbb;    // global batch
    const int jglob = jbase + fj;

    const int slot = (dir * 4 + quarter) * 32;
    unsigned gbase = 0;
    if (qtid == 0) {
        asm volatile("ld.acquire.gpu.global.u32 %0, [%1];"
                     : "=r"(gbase) : "l"(&g_gen4[slot]) : "memory");
    }
    float c_state = 0.f;
    __syncthreads();                                     // w ready
    const int barid = 1 + quarter;

    for (int t = 0; t < SEQ; ++t) {
        const int t_eff = dir ? (SEQ - 1 - t) : t;
        const float* Grow = g_G + (size_t)(fb * SEQ + t_eff) * GN + dir * G4H;
        float pg0 = __ldg(Grow + jglob);
        float pg1 = __ldg(Grow + 512 + jglob);
        float pg2 = __ldg(Grow + 1024 + jglob);
        float pg3 = __ldg(Grow + 1536 + jglob);

        float d0 = 0.f, d1 = 0.f, d2 = 0.f, d3 = 0.f;
        if (t > 0) {
            if (qtid == 0) {
                unsigned v;
                do {
                    asm volatile("ld.acquire.gpu.global.u32 %0, [%1];"
                                 : "=r"(v) : "l"(&g_gen4[slot]) : "memory");
                } while ((unsigned)(v - gbase) < (unsigned)t);
            }
            asm volatile("bar.sync %0, %1;" :: "r"(barid), "r"(64) : "memory");
            // stage this quarter's 8 h rows, k-swizzled
            const int prev_te = dir ? (t_eff + 1) : (t_eff - 1);
            const float* hsrc = g_hseq + (size_t)((dir * SEQ + prev_te) * BSZ + quarter * 8) * HIDD;
            for (int idx = qtid; idx < 8 * 128; idx += 64) {
                int b = idx >> 7;
                int q4 = idx & 127;
                float4 v = __ldcg((const float4*)(hsrc + b * HIDD + q4 * 4));
                *(float4*)&sh[b * RS + q4 * 4 + 4 * (q4 >> 3)] = v;
            }
            asm volatile("bar.sync %0, %1;" :: "r"(barid), "r"(64) : "memory");
            // dot: 4 gate-rows x 8 batches x 64 k (two 32-k swizzle blocks)
            u64v2 acc2[4][8];
#pragma unroll
            for (int g = 0; g < 4; ++g)
#pragma unroll
                for (int bb = 0; bb < 8; ++bb) acc2[g][bb] = 0ull;
            const float* w0p = &sw[jj * RS + kb];
            const float* w1p = w0p + 8 * RS;
            const float* w2p = w0p + 16 * RS;
            const float* w3p = w0p + 24 * RS;
            const float* hp  = &sh[kb];
#pragma unroll
            for (int sb = 0; sb < 2; ++sb) {
                const int so = sb * 36;
#pragma unroll
                for (int kk = 0; kk < 32; kk += 4) {
                    ulonglong2 w0 = *(const ulonglong2*)(w0p + so + kk);
                    ulonglong2 w1 = *(const ulonglong2*)(w1p + so + kk);
                    ulonglong2 w2 = *(const ulonglong2*)(w2p + so + kk);
                    ulonglong2 w3 = *(const ulonglong2*)(w3p + so + kk);
#pragma unroll
                    for (int bb = 0; bb < 8; ++bb) {
                        ulonglong2 h = *(const ulonglong2*)(hp + bb * RS + so + kk);
                        fma2_(acc2[0][bb], w0.x, h.x); fma2_(acc2[0][bb], w0.y, h.y);
                        fma2_(acc2[1][bb], w1.x, h.x); fma2_(acc2[1][bb], w1.y, h.y);
                        fma2_(acc2[2][bb], w2.x, h.x); fma2_(acc2[2][bb], w2.y, h.y);
                        fma2_(acc2[3][bb], w3.x, h.x); fma2_(acc2[3][bb], w3.y, h.y);
                    }
                }
            }
            float* rp = &red[(kseg * 8 + jj) * 36];
#pragma unroll
            for (int g = 0; g < 4; ++g) {
                float s0 = unpack_sum_(acc2[g][0]);
                float s1 = unpack_sum_(acc2[g][1]);
                float s2 = unpack_sum_(acc2[g][2]);
                float s3 = unpack_sum_(acc2[g][3]);
                float s4 = unpack_sum_(acc2[g][4]);
                float s5 = unpack_sum_(acc2[g][5]);
                float s6 = unpack_sum_(acc2[g][6]);
                float s7 = unpack_sum_(acc2[g][7]);
                // transpose write: red[..][g*8 + bb] = acc[g][bb]
                rp[g * 8 + 0] = s0; rp[g * 8 + 1] = s1;
                rp[g * 8 + 2] = s2; rp[g * 8 + 3] = s3;
                rp[g * 8 + 4] = s4; rp[g * 8 + 5] = s5;
                rp[g * 8 + 6] = s6; rp[g * 8 + 7] = s7;
            }
            asm volatile("bar.sync %0, %1;" :: "r"(barid), "r"(64) : "memory");
#pragma unroll
            for (int s = 0; s < 8; ++s) {
                const float* rr = &red[(s * 8 + fj) * 36];
                d0 += rr[fbb];
                d1 += rr[8 + fbb];
                d2 += rr[16 + fbb];
                d3 += rr[24 + fbb];
            }
        }
        {
            float gi = pg0 + d0;
            float gf = pg1 + d1;
            float gg = pg2 + d2;
            float go = pg3 + d3;
            float iv = sigmoidf_(gi);
            float fv = sigmoidf_(gf);
            float ov = sigmoidf_(go);
            float gv = tanhf(gg);
            c_state = fv * c_state + iv * gv;
            float hv = ov * tanhf(c_state);
            __stcg(&g_hseq[(size_t)((dir * SEQ + t_eff) * BSZ + fb) * HIDD + jglob], hv);
        }
        asm volatile("bar.sync %0, %1;" :: "r"(barid), "r"(64) : "memory");
        if (qtid == 0) {
            unsigned old;
            asm volatile("atom.release.gpu.global.add.u32 %0, [%1], %2;"
                         : "=r"(old) : "l"(&g_cnt4[slot]), "r"(1u) : "memory");
            if (old == 63u) {
                asm volatile("st.global.u32 [%0], %1;"
                             :: "l"(&g_cnt4[slot]), "r"(0u) : "memory");
                unsigned ng = gbase + (unsigned)t + 1u;
                asm volatile("st.release.gpu.global.u32 [%0], %1;"
                             :: "l"(&g_gen4[slot]), "r"(ng) : "memory");
            }
        }
    }
}

// =====================================================================
// Kernel 3: emissions
// =====================================================================
__device__ __forceinline__ float dot4_(float4 a, float4 b) {
    return a.x * b.x + a.y * b.y + a.z * b.z + a.w * b.w;
}

__global__ __launch_bounds__(256) void emis_k(
    const float* __restrict__ lw, const float* __restrict__ lb)
{
    __shared__ float shh[32 * 132];
    __shared__ float shw[48 * 132];
    const int tid = threadIdx.x;
    const int blk = blockIdx.x;
    const int b = blk >> 3;
    const int s0 = (blk & 7) * 32;
    const int tt = tid & 15;
    const int tg = tid >> 4;
    float acc[2][3] = {{0.f, 0.f, 0.f}, {0.f, 0.f, 0.f}};

    for (int kc = 0; kc < 1024; kc += 128) {
        __syncthreads();
        const int dk = kc >> 9;
        const int ko = kc & 511;
        for (int idx = tid; idx < 32 * 32; idx += 256) {
            int ti = idx >> 5;
            int q = (idx & 31) * 4;
            *(float4*)&shh[ti * 132 + q] =
                *(const float4*)&g_hseq[(size_t)((dk * SEQ + (s0 + ti)) * BSZ + b) * HIDD + ko + q];
        }
        for (int idx = tid; idx < 48 * 32; idx += 256) {
            int tag = idx >> 5;
            int q = (idx & 31) * 4;
            float4 v = make_float4(0.f, 0.f, 0.f, 0.f);
            if (tag < NTAG) v = *(const float4*)&lw[(size_t)tag * 1024 + kc + q];
            *(float4*)&shw[tag * 132 + q] = v;
        }
        __syncthreads();
#pragma unroll 8
        for (int kk = 0; kk < 128; kk += 4) {
            float4 h0 = *(const float4*)&shh[tt * 132 + kk];
            float4 h1 = *(const float4*)&shh[(tt + 16) * 132 + kk];
            float4 w0 = *(const float4*)&shw[tg * 132 + kk];
            float4 w1 = *(const float4*)&shw[(tg + 16) * 132 + kk];
            float4 w2 = *(const float4*)&shw[(tg + 32) * 132 + kk];
            acc[0][0] += dot4_(h0, w0); acc[0][1] += dot4_(h0, w1); acc[0][2] += dot4_(h0, w2);
            acc[1][0] += dot4_(h1, w0); acc[1][1] += dot4_(h1, w1); acc[1][2] += dot4_(h1, w2);
        }
    }
#pragma unroll
    for (int ti = 0; ti < 2; ++ti) {
        int token = b * SEQ + s0 + tt + ti * 16;
#pragma unroll
        for (int c = 0; c < 3; ++c) {
            int tag = tg + c * 16;
            if (tag < NTAG)
                g_em[(size_t)token * NTAG + tag] = acc[ti][c] + lb[tag];
        }
    }
}

// =====================================================================
// Kernel 4: CRF — one WARP per batch, smem alpha ping-pong (proven),
// with 4-way SPLIT accumulator chains in the per-step dot.
// =====================================================================
__global__ __launch_bounds__(128) void crf_k(
    const int* __restrict__ tags, const float* __restrict__ st,
    const float* __restrict__ et, const float* __restrict__ tr)
{
    __shared__ float str[NTAG * NTAG];
    __shared__ float sE[NTAG * 48];
    __shared__ float sa[4][2][48];
    const int tid = threadIdx.x;
    const int wid = tid >> 5;
    const int lane = tid & 31;
    const int b = blockIdx.x * 4 + wid;
    const int* tg = tags + b * SEQ;

    for (int i = tid; i < NTAG * NTAG; i += 128) str[i] = tr[i];
    __syncthreads();
    for (int idx = tid; idx < NTAG * NTAG; idx += 128) {
        int i = idx / NTAG, col = idx % NTAG;
        sE[i * 48 + col] = __expf(str[idx]);
    }
    __syncthreads();

    float part = 0.f;
    for (int s = lane; s < SEQ; s += 32) {
        int cur = tg[s];
        part += g_em[(size_t)(b * SEQ + s) * NTAG + cur];
        if (s + 1 < SEQ) part += str[cur * NTAG + tg[s + 1]];
    }
#pragma unroll
    for (int off = 16; off; off >>= 1)
        part += __shfl_xor_sync(0xffffffffu, part, off);

    const int c0 = lane;
    const bool has1 = (lane < 13);
    const int c1 = has1 ? lane + 32 : lane;
    float* a0 = sa[wid][0];
    float* a1 = sa[wid][1];

    float i0 = st[c0] + g_em[(size_t)(b * SEQ) * NTAG + c0];
    float i1 = has1 ? (st[c1] + g_em[(size_t)(b * SEQ) * NTAG + c1]) : -1e30f;
    float m = fmaxf(i0, i1);
#pragma unroll
    for (int off = 16; off; off >>= 1)
        m = fmaxf(m, __shfl_xor_sync(0xffffffffu, m, off));
    float logacc = m;
    a0[c0] = __expf(i0 - m);
    if (has1) a0[c1] = __expf(i1 - m);
    __syncwarp();

    float e0 = g_em[(size_t)(b * SEQ + 1) * NTAG + c0];
    float e1 = has1 ? g_em[(size_t)(b * SEQ + 1) * NTAG + c1] : 0.f;
    int cur = 0;
    for (int t = 1; t < SEQ; ++t) {
        float n0 = 0.f, n1 = 0.f;
        if (t + 1 < SEQ) {
            n0 = g_em[(size_t)(b * SEQ + t + 1) * NTAG + c0];
            if (has1) n1 = g_em[(size_t)(b * SEQ + t + 1) * NTAG + c1];
        }
        const float* a = cur ? a1 : a0;
        float* an = cur ? a0 : a1;
        // 4-way split accumulator chains (11 deep each)
        float s0a = 0.f, s0b = 0.f, s0c = 0.f, s0d = 0.f;
        float s1a = 0.f, s1b = 0.f, s1c = 0.f, s1d = 0.f;
#pragma unroll
        for (int i = 0; i < 44; i += 4) {
            float ai0 = a[i], ai1 = a[i + 1], ai2 = a[i + 2], ai3 = a[i + 3];
            s0a += sE[(i    ) * 48 + c0] * ai0;  s1a += sE[(i    ) * 48 + c1] * ai0;
            s0b += sE[(i + 1) * 48 + c0] * ai1;  s1b += sE[(i + 1) * 48 + c1] * ai1;
            s0c += sE[(i + 2) * 48 + c0] * ai2;  s1c += sE[(i + 2) * 48 + c1] * ai2;
            s0d += sE[(i + 3) * 48 + c0] * ai3;  s1d += sE[(i + 3) * 48 + c1] * ai3;
        }
        float a44 = a[44];
        s0a += sE[44 * 48 + c0] * a44;
        s1a += sE[44 * 48 + c1] * a44;
        float s0 = (s0a + s0b) + (s0c + s0d);
        float s1 = (s1a + s1b) + (s1c + s1d);
        float v0 = s0 * __expf(e0);
        an[c0] = v0;
        float v1 = 0.f;
        if (has1) { v1 = s1 * __expf(e1); an[c1] = v1; }
        __syncwarp();
        cur ^= 1;
        if ((t & 7) == 0) {
            float mm = fmaxf(v0, v1);
#pragma unroll
            for (int off = 16; off; off >>= 1)
                mm = fmaxf(mm, __shfl_xor_sync(0xffffffffu, mm, off));
            float inv = 1.f / mm;
            float* ac = cur ? a1 : a0;
            ac[c0] *= inv;
            if (has1) ac[c1] *= inv;
            logacc += __logf(mm);
            __syncwarp();
        }
        e0 = n0; e1 = n1;
    }

    const float* af = cur ? a1 : a0;
    float ssum = af[c0] * __expf(et[c0]);
    if (has1) ssum += af[c1] * __expf(et[c1]);
#pragma unroll
    for (int off = 16; off; off >>= 1)
        ssum += __shfl_xor_sync(0xffffffffu, ssum, off);

    if (lane == 0) {
        float sc = part + st[tg[0]] + et[tg[SEQ - 1]];
        float logZ = logacc + __logf(ssum);
        g_loss[b] = logZ - sc;
    }
}

__global__ void final_reduce(float* __restrict__ out)
{
    if (threadIdx.x == 0) {
        float s = 0.f;
        for (int i = 0; i < BSZ; ++i) s += g_loss[i];
        out[0] = s / (float)BSZ;
    }
}

// =====================================================================
extern "C" void kernel_launch(void* const* d_in, const int* in_sizes, int n_in,
                              void* d_out, int out_size)
{
    (void)in_sizes; (void)n_in; (void)out_size;
    const int*   x   = (const int*)d_in[0];
    const int*   tgs = (const int*)d_in[1];
    const float* emb = (const float*)d_in[2];
    const float* wif = (const float*)d_in[3];
    const float* whf = (const float*)d_in[4];
    const float* bf  = (const float*)d_in[5];
    const float* wib = (const float*)d_in[6];
    const float* whb = (const float*)d_in[7];
    const float* bb  = (const float*)d_in[8];
    const float* lw  = (const float*)d_in[9];
    const float* lb  = (const float*)d_in[10];
    const float* st  = (const float*)d_in[11];
    const float* et  = (const float*)d_in[12];
    const float* tr  = (const float*)d_in[13];
    float* out = (float*)d_out;

    const int rec_smem = (64 * RS + 4 * 8 * 8 * 36) * 4;   // 183296 B
    cudaFuncSetAttribute(lstm_rec, cudaFuncAttributeMaxDynamicSharedMemorySize, rec_smem);

    dim3 gemm_grid(32, 64);
    gemm_in<<<gemm_grid, 256>>>(x, emb, wif, wib, bf, bb);
    lstm_rec<<<128, 256, rec_smem>>>(whf, whb);
    emis_k<<<256, 256>>>(lw, lb);
    crf_k<<<8, 128>>>(tgs, st, et, tr);
    final_reduce<<<1, 32>>>(out);
}

// round 16
// speedup vs baseline: 1.1201x; 1.0176x over previous
#include <cuda_runtime.h>
#include <cstdint>
#include <cstddef>

#define BSZ 32
#define SEQ 256
#define EMBD 256
#define HIDD 512
#define NTAG 45
#define NTOK (BSZ*SEQ)     // 8192
#define G4H  2048          // 4*HID
#define GN   4096          // both directions
#define RS   572           // lstm smem row stride (floats)

typedef unsigned long long u64v2;   // packed f32x2

__device__ __forceinline__ void fma2_(u64v2& d, u64v2 a, u64v2 b) {
    asm("fma.rn.f32x2 %0, %1, %2, %0;" : "+l"(d) : "l"(a), "l"(b));
}
__device__ __forceinline__ float unpack_sum_(u64v2 v) {
    float lo, hi;
    asm("mov.b64 {%0, %1}, %2;" : "=f"(lo), "=f"(hi) : "l"(v));
    return lo + hi;
}
__device__ __forceinline__ u64v2 pack2_(float lo, float hi) {
    u64v2 r;
    asm("mov.b64 %0, {%1, %2};" : "=l"(r) : "f"(lo), "f"(hi));
    return r;
}

// ---------------- scratch ----------------
__device__ __align__(16) float g_G[(size_t)NTOK * GN];           // input proj + bias
__device__ __align__(16) float g_hseq[2 * SEQ * BSZ * HIDD];     // [dir][t][b][h]
__device__ __align__(16) float g_em[(size_t)NTOK * NTAG];        // emissions
__device__ float g_loss[BSZ];
__device__ unsigned g_cnt4[8 * 32];                              // flat barrier counters (8 slots)
__device__ unsigned g_gen4[8 * 32];                              // monotonic generations

// =====================================================================
// Kernel 1: G[token][n] = dot(emb[x[token]], W[n]) + bias[n]  (f32x2)
// =====================================================================
__global__ __launch_bounds__(256, 2) void gemm_in(
    const int* __restrict__ x, const float* __restrict__ emb,
    const float* __restrict__ wf, const float* __restrict__ wb,
    const float* __restrict__ bf, const float* __restrict__ bb)
{
    __shared__ float sA[16 * 132];
    __shared__ float sW[16 * 132];
    const int tid = threadIdx.x;
    const int bx = blockIdx.x;
    const int by = blockIdx.y;
    const int tx = tid & 15, ty = tid >> 4;

    u64v2 acc2[8][4];
#pragma unroll
    for (int i = 0; i < 8; ++i)
#pragma unroll
        for (int j = 0; j < 4; ++j) acc2[i][j] = 0ull;

    const int f4a = tid * 2, f4b = tid * 2 + 1;
    const int ra = f4a >> 2, qa = (f4a & 3) * 4;
    const int rb = f4b >> 2, qb = (f4b & 3) * 4;
    const float* arow_a = emb + (size_t)x[by * 128 + ra] * EMBD;
    const float* arow_b = emb + (size_t)x[by * 128 + rb] * EMBD;
    const int na = bx * 128 + ra, nb = bx * 128 + rb;
    const float* wrow_a = (na < G4H) ? (wf + (size_t)na * EMBD) : (wb + (size_t)(na - G4H) * EMBD);
    const float* wrow_b = (nb < G4H) ? (wf + (size_t)nb * EMBD) : (wb + (size_t)(nb - G4H) * EMBD);

    for (int kb = 0; kb < EMBD; kb += 16) {
        __syncthreads();
        float4 va = *(const float4*)(arow_a + kb + qa);
        float4 vb = *(const float4*)(arow_b + kb + qb);
        float4 wa = *(const float4*)(wrow_a + kb + qa);
        float4 wv = *(const float4*)(wrow_b + kb + qb);
        sA[(qa + 0) * 132 + ra] = va.x; sA[(qa + 1) * 132 + ra] = va.y;
        sA[(qa + 2) * 132 + ra] = va.z; sA[(qa + 3) * 132 + ra] = va.w;
        sA[(qb + 0) * 132 + rb] = vb.x; sA[(qb + 1) * 132 + rb] = vb.y;
        sA[(qb + 2) * 132 + rb] = vb.z; sA[(qb + 3) * 132 + rb] = vb.w;
        sW[(qa + 0) * 132 + ra] = wa.x; sW[(qa + 1) * 132 + ra] = wa.y;
        sW[(qa + 2) * 132 + ra] = wa.z; sW[(qa + 3) * 132 + ra] = wa.w;
        sW[(qb + 0) * 132 + rb] = wv.x; sW[(qb + 1) * 132 + rb] = wv.y;
        sW[(qb + 2) * 132 + rb] = wv.z; sW[(qb + 3) * 132 + rb] = wv.w;
        __syncthreads();
#pragma unroll
        for (int kk = 0; kk < 16; ++kk) {
            float4 a0 = *(const float4*)&sA[kk * 132 + ty * 8];
            float4 a1 = *(const float4*)&sA[kk * 132 + ty * 8 + 4];
            ulonglong2 b0 = *(const ulonglong2*)&sW[kk * 132 + tx * 8];
            ulonglong2 b1 = *(const ulonglong2*)&sW[kk * 132 + tx * 8 + 4];
            float av[8] = {a0.x, a0.y, a0.z, a0.w, a1.x, a1.y, a1.z, a1.w};
#pragma unroll
            for (int i = 0; i < 8; ++i) {
                u64v2 aa = pack2_(av[i], av[i]);
                fma2_(acc2[i][0], aa, b0.x);
                fma2_(acc2[i][1], aa, b0.y);
                fma2_(acc2[i][2], aa, b1.x);
                fma2_(acc2[i][3], aa, b1.y);
            }
        }
    }
    const int m0 = by * 128 + ty * 8;
    const int n0 = bx * 128 + tx * 8;
    // hoist biases (8 n values per thread)
    float bias[8];
#pragma unroll
    for (int j = 0; j < 8; ++j) {
        int n = n0 + j;
        bias[j] = (n < G4H) ? bf[n] : bb[n - G4H];
    }
#pragma unroll
    for (int i = 0; i < 8; ++i) {
        float* dst = g_G + (size_t)(m0 + i) * GN + n0;
        float v[8];
#pragma unroll
        for (int p = 0; p < 4; ++p) {
            float lo, hi;
            asm("mov.b64 {%0, %1}, %2;" : "=f"(lo), "=f"(hi) : "l"(acc2[i][p]));
            v[2 * p] = lo + bias[2 * p];
            v[2 * p + 1] = hi + bias[2 * p + 1];
        }
        *(float4*)dst       = make_float4(v[0], v[1], v[2], v[3]);
        *(float4*)(dst + 4) = make_float4(v[4], v[5], v[6], v[7]);
    }
}

// =====================================================================
// Kernel 2: persistent bidirectional LSTM — FOUR independent streams
// (quarters of 8 batches, 2 warps each). All-lanes acquire-poll on the
// generation word (no named barrier for the wait).
// =====================================================================
__device__ __forceinline__ float sigmoidf_(float v) { return 1.f / (1.f + __expf(-v)); }

__global__ __launch_bounds__(256) void lstm_rec(
    const float* __restrict__ whf, const float* __restrict__ whb)
{
    extern __shared__ float smemf[];
    float* sw = smemf;                                   // 32 rows x RS (shared)

    const int tid = threadIdx.x;
    const int dir = blockIdx.x >> 6;
    const int blk = blockIdx.x & 63;
    const int jbase = blk * 8;
    const int quarter = tid >> 6;                        // 0..3 (8 batches each)
    const int qtid = tid & 63;
    const float* whh = dir ? whb : whf;

    float* sh  = smemf + (32 + quarter * 8) * RS;        // 8 rows x RS per quarter
    float* red = smemf + 64 * RS + quarter * (8 * 8 * 36); // [8 kseg][8 jj] x 36

    for (int idx = tid; idx < 32 * 128; idx += 256) {
        int row = idx >> 7;
        int q4 = idx & 127;
        int g = row >> 3, j = row & 7;
        float4 v = *(const float4*)(whh + (size_t)(g * 512 + jbase + j) * HIDD + q4 * 4);
        *(float4*)&sw[row * RS + q4 * 4 + 4 * (q4 >> 3)] = v;
    }

    const int kseg = qtid >> 3;          // 0..7
    const int jj = qtid & 7;
    const int kb = kseg * 72;            // swizzled 64-k base

    const int fj = qtid & 7;
    const int fbb = qtid >> 3;           // 0..7 batch within quarter
    const int fb = quarter * 8 + fbb;
    const int jglob = jbase + fj;

    const int slot = (dir * 4 + quarter) * 32;
    unsigned gbase;
    asm volatile("ld.acquire.gpu.global.u32 %0, [%1];"
                 : "=r"(gbase) : "l"(&g_gen4[slot]) : "memory");
    float c_state = 0.f;
    __syncthreads();                                     // w ready
    const int barid = 1 + quarter;

    for (int t = 0; t < SEQ; ++t) {
        const int t_eff = dir ? (SEQ - 1 - t) : t;
        const float* Grow = g_G + (size_t)(fb * SEQ + t_eff) * GN + dir * G4H;
        float pg0 = __ldg(Grow + jglob);
        float pg1 = __ldg(Grow + 512 + jglob);
        float pg2 = __ldg(Grow + 1024 + jglob);
        float pg3 = __ldg(Grow + 1536 + jglob);

        float d0 = 0.f, d1 = 0.f, d2 = 0.f, d3 = 0.f;
        if (t > 0) {
            // all-lanes acquire poll (same cacheline -> 1 request/warp)
            unsigned v;
            do {
                asm volatile("ld.acquire.gpu.global.u32 %0, [%1];"
                             : "=r"(v) : "l"(&g_gen4[slot]) : "memory");
            } while ((unsigned)(v - gbase) < (unsigned)t);
            // stage this quarter's 8 h rows, k-swizzled
            const int prev_te = dir ? (t_eff + 1) : (t_eff - 1);
            const float* hsrc = g_hseq + (size_t)((dir * SEQ + prev_te) * BSZ + quarter * 8) * HIDD;
            for (int idx = qtid; idx < 8 * 128; idx += 64) {
                int b = idx >> 7;
                int q4 = idx & 127;
                float4 hv = __ldcg((const float4*)(hsrc + b * HIDD + q4 * 4));
                *(float4*)&sh[b * RS + q4 * 4 + 4 * (q4 >> 3)] = hv;
            }
            asm volatile("bar.sync %0, %1;" :: "r"(barid), "r"(64) : "memory");
            u64v2 acc2[4][8];
#pragma unroll
            for (int g = 0; g < 4; ++g)
#pragma unroll
                for (int bb = 0; bb < 8; ++bb) acc2[g][bb] = 0ull;
            const float* w0p = &sw[jj * RS + kb];
            const float* w1p = w0p + 8 * RS;
            const float* w2p = w0p + 16 * RS;
            const float* w3p = w0p + 24 * RS;
            const float* hp  = &sh[kb];
#pragma unroll
            for (int sb = 0; sb < 2; ++sb) {
                const int so = sb * 36;
#pragma unroll
                for (int kk = 0; kk < 32; kk += 4) {
                    ulonglong2 w0 = *(const ulonglong2*)(w0p + so + kk);
                    ulonglong2 w1 = *(const ulonglong2*)(w1p + so + kk);
                    ulonglong2 w2 = *(const ulonglong2*)(w2p + so + kk);
                    ulonglong2 w3 = *(const ulonglong2*)(w3p + so + kk);
#pragma unroll
                    for (int bb = 0; bb < 8; ++bb) {
                        ulonglong2 h = *(const ulonglong2*)(hp + bb * RS + so + kk);
                        fma2_(acc2[0][bb], w0.x, h.x); fma2_(acc2[0][bb], w0.y, h.y);
                        fma2_(acc2[1][bb], w1.x, h.x); fma2_(acc2[1][bb], w1.y, h.y);
                        fma2_(acc2[2][bb], w2.x, h.x); fma2_(acc2[2][bb], w2.y, h.y);
                        fma2_(acc2[3][bb], w3.x, h.x); fma2_(acc2[3][bb], w3.y, h.y);
                    }
                }
            }
            float* rp = &red[(kseg * 8 + jj) * 36];
#pragma unroll
            for (int g = 0; g < 4; ++g) {
                float s0 = unpack_sum_(acc2[g][0]);
                float s1 = unpack_sum_(acc2[g][1]);
                float s2 = unpack_sum_(acc2[g][2]);
                float s3 = unpack_sum_(acc2[g][3]);
                float s4 = unpack_sum_(acc2[g][4]);
                float s5 = unpack_sum_(acc2[g][5]);
                float s6 = unpack_sum_(acc2[g][6]);
                float s7 = unpack_sum_(acc2[g][7]);
                rp[g * 8 + 0] = s0; rp[g * 8 + 1] = s1;
                rp[g * 8 + 2] = s2; rp[g * 8 + 3] = s3;
                rp[g * 8 + 4] = s4; rp[g * 8 + 5] = s5;
                rp[g * 8 + 6] = s6; rp[g * 8 + 7] = s7;
            }
            asm volatile("bar.sync %0, %1;" :: "r"(barid), "r"(64) : "memory");
#pragma unroll
            for (int s = 0; s < 8; ++s) {
                const float* rr = &red[(s * 8 + fj) * 36];
                d0 += rr[fbb];
                d1 += rr[8 + fbb];
                d2 += rr[16 + fbb];
                d3 += rr[24 + fbb];
            }
        }
        {
            float gi = pg0 + d0;
            float gf = pg1 + d1;
            float gg = pg2 + d2;
            float go = pg3 + d3;
            float iv = sigmoidf_(gi);
            float fv = sigmoidf_(gf);
            float ov = sigmoidf_(go);
            float gv = tanhf(gg);
            c_state = fv * c_state + iv * gv;
            float hv = ov * tanhf(c_state);
            __stcg(&g_hseq[(size_t)((dir * SEQ + t_eff) * BSZ + fb) * HIDD + jglob], hv);
        }
        asm volatile("bar.sync %0, %1;" :: "r"(barid), "r"(64) : "memory");
        if (qtid == 0) {
            unsigned old;
            asm volatile("atom.release.gpu.global.add.u32 %0, [%1], %2;"
                         : "=r"(old) : "l"(&g_cnt4[slot]), "r"(1u) : "memory");
            if (old == 63u) {
                asm volatile("st.global.u32 [%0], %1;"
                             :: "l"(&g_cnt4[slot]), "r"(0u) : "memory");
                unsigned ng = gbase + (unsigned)t + 1u;
                asm volatile("st.release.gpu.global.u32 [%0], %1;"
                             :: "l"(&g_gen4[slot]), "r"(ng) : "memory");
            }
        }
    }
}

// =====================================================================
// Kernel 3: emissions
// =====================================================================
__device__ __forceinline__ float dot4_(float4 a, float4 b) {
    return a.x * b.x + a.y * b.y + a.z * b.z + a.w * b.w;
}

__global__ __launch_bounds__(256) void emis_k(
    const float* __restrict__ lw, const float* __restrict__ lb)
{
    __shared__ float shh[32 * 132];
    __shared__ float shw[48 * 132];
    const int tid = threadIdx.x;
    const int blk = blockIdx.x;
    const int b = blk >> 3;
    const int s0 = (blk & 7) * 32;
    const int tt = tid & 15;
    const int tg = tid >> 4;
    float acc[2][3] = {{0.f, 0.f, 0.f}, {0.f, 0.f, 0.f}};

    for (int kc = 0; kc < 1024; kc += 128) {
        __syncthreads();
        const int dk = kc >> 9;
        const int ko = kc & 511;
        for (int idx = tid; idx < 32 * 32; idx += 256) {
            int ti = idx >> 5;
            int q = (idx & 31) * 4;
            *(float4*)&shh[ti * 132 + q] =
                *(const float4*)&g_hseq[(size_t)((dk * SEQ + (s0 + ti)) * BSZ + b) * HIDD + ko + q];
        }
        for (int idx = tid; idx < 48 * 32; idx += 256) {
            int tag = idx >> 5;
            int q = (idx & 31) * 4;
            float4 v = make_float4(0.f, 0.f, 0.f, 0.f);
            if (tag < NTAG) v = *(const float4*)&lw[(size_t)tag * 1024 + kc + q];
            *(float4*)&shw[tag * 132 + q] = v;
        }
        __syncthreads();
#pragma unroll 8
        for (int kk = 0; kk < 128; kk += 4) {
            float4 h0 = *(const float4*)&shh[tt * 132 + kk];
            float4 h1 = *(const float4*)&shh[(tt + 16) * 132 + kk];
            float4 w0 = *(const float4*)&shw[tg * 132 + kk];
            float4 w1 = *(const float4*)&shw[(tg + 16) * 132 + kk];
            float4 w2 = *(const float4*)&shw[(tg + 32) * 132 + kk];
            acc[0][0] += dot4_(h0, w0); acc[0][1] += dot4_(h0, w1); acc[0][2] += dot4_(h0, w2);
            acc[1][0] += dot4_(h1, w0); acc[1][1] += dot4_(h1, w1); acc[1][2] += dot4_(h1, w2);
        }
    }
#pragma unroll
    for (int ti = 0; ti < 2; ++ti) {
        int token = b * SEQ + s0 + tt + ti * 16;
#pragma unroll
        for (int c = 0; c < 3; ++c) {
            int tag = tg + c * 16;
            if (tag < NTAG)
                g_em[(size_t)token * NTAG + tag] = acc[ti][c] + lb[tag];
        }
    }
}

// =====================================================================
// Kernel 4: CRF — PROVEN R12 version (one warp/batch, smem alpha
// ping-pong, simple chains, lazy renorm every 8 steps). Do not touch.
// =====================================================================
__global__ __launch_bounds__(128) void crf_k(
    const int* __restrict__ tags, const float* __restrict__ st,
    const float* __restrict__ et, const float* __restrict__ tr)
{
    __shared__ float str[NTAG * NTAG];
    __shared__ float sE[NTAG * 48];
    __shared__ float sa[4][2][48];
    const int tid = threadIdx.x;
    const int wid = tid >> 5;
    const int lane = tid & 31;
    const int b = blockIdx.x * 4 + wid;
    const int* tg = tags + b * SEQ;

    for (int i = tid; i < NTAG * NTAG; i += 128) str[i] = tr[i];
    __syncthreads();
    for (int idx = tid; idx < NTAG * NTAG; idx += 128) {
        int i = idx / NTAG, col = idx % NTAG;
        sE[i * 48 + col] = __expf(str[idx]);
    }
    __syncthreads();

    float part = 0.f;
    for (int s = lane; s < SEQ; s += 32) {
        int cur = tg[s];
        part += g_em[(size_t)(b * SEQ + s) * NTAG + cur];
        if (s + 1 < SEQ) part += str[cur * NTAG + tg[s + 1]];
    }
#pragma unroll
    for (int off = 16; off; off >>= 1)
        part += __shfl_xor_sync(0xffffffffu, part, off);

    const int c0 = lane;
    const bool has1 = (lane < 13);
    const int c1 = has1 ? lane + 32 : lane;
    float* a0 = sa[wid][0];
    float* a1 = sa[wid][1];

    float i0 = st[c0] + g_em[(size_t)(b * SEQ) * NTAG + c0];
    float i1 = has1 ? (st[c1] + g_em[(size_t)(b * SEQ) * NTAG + c1]) : -1e30f;
    float m = fmaxf(i0, i1);
#pragma unroll
    for (int off = 16; off; off >>= 1)
        m = fmaxf(m, __shfl_xor_sync(0xffffffffu, m, off));
    float logacc = m;
    a0[c0] = __expf(i0 - m);
    if (has1) a0[c1] = __expf(i1 - m);
    __syncwarp();

    float e0 = g_em[(size_t)(b * SEQ + 1) * NTAG + c0];
    float e1 = has1 ? g_em[(size_t)(b * SEQ + 1) * NTAG + c1] : 0.f;
    int cur = 0;
    for (int t = 1; t < SEQ; ++t) {
        float n0 = 0.f, n1 = 0.f;
        if (t + 1 < SEQ) {
            n0 = g_em[(size_t)(b * SEQ + t + 1) * NTAG + c0];
            if (has1) n1 = g_em[(size_t)(b * SEQ + t + 1) * NTAG + c1];
        }
        const float* a = cur ? a1 : a0;
        float* an = cur ? a0 : a1;
        float s0 = 0.f, s1 = 0.f;
#pragma unroll 9
        for (int i = 0; i < NTAG; ++i) {
            float ai = a[i];
            s0 += sE[i * 48 + c0] * ai;
            s1 += sE[i * 48 + c1] * ai;
        }
        float v0 = s0 * __expf(e0);
        an[c0] = v0;
        float v1 = 0.f;
        if (has1) { v1 = s1 * __expf(e1); an[c1] = v1; }
        __syncwarp();
        cur ^= 1;
        if ((t & 7) == 0) {
            float mm = fmaxf(v0, v1);
#pragma unroll
            for (int off = 16; off; off >>= 1)
                mm = fmaxf(mm, __shfl_xor_sync(0xffffffffu, mm, off));
            float inv = 1.f / mm;
            float* ac = cur ? a1 : a0;
            ac[c0] *= inv;
            if (has1) ac[c1] *= inv;
            logacc += __logf(mm);
            __syncwarp();
        }
        e0 = n0; e1 = n1;
    }

    const float* af = cur ? a1 : a0;
    float ssum = af[c0] * __expf(et[c0]);
    if (has1) ssum += af[c1] * __expf(et[c1]);
#pragma unroll
    for (int off = 16; off; off >>= 1)
        ssum += __shfl_xor_sync(0xffffffffu, ssum, off);

    if (lane == 0) {
        float sc = part + st[tg[0]] + et[tg[SEQ - 1]];
        float logZ = logacc + __logf(ssum);
        g_loss[b] = logZ - sc;
    }
}

__global__ void final_reduce(float* __restrict__ out)
{
    if (threadIdx.x == 0) {
        float s = 0.f;
        for (int i = 0; i < BSZ; ++i) s += g_loss[i];
        out[0] = s / (float)BSZ;
    }
}

// =====================================================================
extern "C" void kernel_launch(void* const* d_in, const int* in_sizes, int n_in,
                              void* d_out, int out_size)
{
    (void)in_sizes; (void)n_in; (void)out_size;
    const int*   x   = (const int*)d_in[0];
    const int*   tgs = (const int*)d_in[1];
    const float* emb = (const float*)d_in[2];
    const float* wif = (const float*)d_in[3];
    const float* whf = (const float*)d_in[4];
    const float* bf  = (const float*)d_in[5];
    const float* wib = (const float*)d_in[6];
    const float* whb = (const float*)d_in[7];
    const float* bb  = (const float*)d_in[8];
    const float* lw  = (const float*)d_in[9];
    const float* lb  = (const float*)d_in[10];
    const float* st  = (const float*)d_in[11];
    const float* et  = (const float*)d_in[12];
    const float* tr  = (const float*)d_in[13];
    float* out = (float*)d_out;

    const int rec_smem = (64 * RS + 4 * 8 * 8 * 36) * 4;   // 183296 B
    cudaFuncSetAttribute(lstm_rec, cudaFuncAttributeMaxDynamicSharedMemorySize, rec_smem);

    dim3 gemm_grid(32, 64);
    gemm_in<<<gemm_grid, 256>>>(x, emb, wif, wib, bf, bb);
    lstm_rec<<<128, 256, rec_smem>>>(whf, whb);
    emis_k<<<256, 256>>>(lw, lb);
    crf_k<<<8, 128>>>(tgs, st, et, tr);
    final_reduce<<<1, 32>>>(out);
}